// round 11
// baseline (speedup 1.0000x reference)
#include <cuda_runtime.h>
#include <cstdint>

#define MAXN 4096
#define MAXD 256
#define PAIR_CAP 262144
#define SSTRIDE 132   // shared tile row stride (floats), 16B-aligned, conflict-reduced

// -------- scratch (device globals; no allocation allowed) --------
__device__ float  g_norm[MAXN * MAXD];
__device__ float  g_negsum[MAXN];
__device__ int    g_lab[MAXN];
__device__ int    g_paircnt;
__device__ int    g_pair_i[PAIR_CAP];
__device__ float  g_pair_s[PAIR_CAP];
__device__ double g_loss;
__device__ int    g_cnt;

// ---------------------------------------------------------------
// K0: detect label width (int64 vs int32) and convert to g_lab[int].
// Labels are in [0, 512). If stored as int64 (little-endian), every odd
// 32-bit word is zero. If int32, odd words are real labels; the chance
// the first 128 odd words are ALL zero is (1/512)^128 ~ 0.
// Deterministic for fixed input. One block.
// ---------------------------------------------------------------
__global__ void __launch_bounds__(256) labels_kernel(const unsigned* __restrict__ w, int n) {
    __shared__ int s_nonzero;
    if (threadIdx.x == 0) s_nonzero = 0;
    __syncthreads();
    // check odd words among the first 256 words
    int idx = 2 * threadIdx.x + 1;           // 1,3,...,511 for 256 threads
    if (threadIdx.x < 128 && idx < 2 * n) {
        if (w[idx] != 0u) atomicOr(&s_nonzero, 1);
    }
    __syncthreads();
    const bool is64 = (s_nonzero == 0);
    for (int i = threadIdx.x; i < n; i += 256) {
        g_lab[i] = is64 ? (int)w[2 * i] : (int)w[i];
    }
}

// ---------------------------------------------------------------
// K1: row-normalize X -> g_norm; zero per-row negsum + global counters.
// One block (64 threads) per row.
// ---------------------------------------------------------------
__global__ void __launch_bounds__(64) normalize_kernel(const float* __restrict__ X,
                                                       int n, int d) {
    int row = blockIdx.x;
    if (row >= n) return;
    const float* xr = X + (size_t)row * d;

    float ss = 0.0f;
    int nq = d >> 2;
    for (int c = threadIdx.x; c < nq; c += 64) {
        float4 v = reinterpret_cast<const float4*>(xr)[c];
        ss += v.x * v.x + v.y * v.y + v.z * v.z + v.w * v.w;
    }
    #pragma unroll
    for (int off = 16; off > 0; off >>= 1)
        ss += __shfl_xor_sync(0xFFFFFFFFu, ss, off);
    __shared__ float sws[2];
    int lane = threadIdx.x & 31, warp = threadIdx.x >> 5;
    if (lane == 0) sws[warp] = ss;
    __syncthreads();
    float tot = sws[0] + sws[1];
    float inv = 1.0f / fmaxf(sqrtf(tot), 1e-12f);

    float* nr = g_norm + (size_t)row * d;
    for (int c = threadIdx.x; c < nq; c += 64) {
        float4 v = reinterpret_cast<const float4*>(xr)[c];
        float4 o;
        o.x = v.x * inv; o.y = v.y * inv; o.z = v.z * inv; o.w = v.w * inv;
        reinterpret_cast<float4*>(nr)[c] = o;
    }

    if (threadIdx.x == 0) {
        g_negsum[row] = 0.0f;
        if (row == 0) { g_paircnt = 0; g_loss = 0.0; g_cnt = 0; }
    }
}

// ---------------------------------------------------------------
// K2: symmetric sim GEMM (upper-triangular tiles only), fused exp,
// masked negative-sum accumulation (both directions via symmetry),
// same-label pair capture. 128x128 tiles, BK=16, 8x8 microtiles.
// ---------------------------------------------------------------
__global__ void __launch_bounds__(256) gemm_kernel(int n, int d) {
    const int ib = blockIdx.y;
    const int jb = blockIdx.x;
    if (jb < ib) return;
    const bool diag = (ib == jb);

    const int i0 = ib * 128;
    const int j0 = jb * 128;

    __shared__ float As[16 * SSTRIDE];
    __shared__ float Bs[16 * SSTRIDE];
    __shared__ int   labI[128], labJ[128];
    __shared__ float sNegR[128], sNegC[128];

    const int tx = threadIdx.x;  // 0..15
    const int ty = threadIdx.y;  // 0..15
    const int tid = ty * 16 + tx;

    if (tid < 128) {
        sNegR[tid] = 0.0f;
        sNegC[tid] = 0.0f;
        labI[tid] = g_lab[i0 + tid];
        labJ[tid] = g_lab[j0 + tid];
    }

    float acc[8][8];
    #pragma unroll
    for (int a = 0; a < 8; ++a)
        #pragma unroll
        for (int b = 0; b < 8; ++b) acc[a][b] = 0.0f;

    const int nk = d / 16;
    for (int kt = 0; kt < nk; ++kt) {
        __syncthreads();
        #pragma unroll
        for (int l = 0; l < 2; ++l) {
            int idx = tid + l * 256;
            int row = idx >> 2;
            int q = idx & 3;
            int kc = kt * 16 + q * 4;
            float4 a4 = *reinterpret_cast<const float4*>(&g_norm[(size_t)(i0 + row) * d + kc]);
            As[(q * 4 + 0) * SSTRIDE + row] = a4.x;
            As[(q * 4 + 1) * SSTRIDE + row] = a4.y;
            As[(q * 4 + 2) * SSTRIDE + row] = a4.z;
            As[(q * 4 + 3) * SSTRIDE + row] = a4.w;
            float4 b4 = *reinterpret_cast<const float4*>(&g_norm[(size_t)(j0 + row) * d + kc]);
            Bs[(q * 4 + 0) * SSTRIDE + row] = b4.x;
            Bs[(q * 4 + 1) * SSTRIDE + row] = b4.y;
            Bs[(q * 4 + 2) * SSTRIDE + row] = b4.z;
            Bs[(q * 4 + 3) * SSTRIDE + row] = b4.w;
        }
        __syncthreads();

        #pragma unroll
        for (int k = 0; k < 16; ++k) {
            float ar[8], br[8];
            float4 t0 = *reinterpret_cast<const float4*>(&As[k * SSTRIDE + ty * 8]);
            float4 t1 = *reinterpret_cast<const float4*>(&As[k * SSTRIDE + ty * 8 + 4]);
            ar[0] = t0.x; ar[1] = t0.y; ar[2] = t0.z; ar[3] = t0.w;
            ar[4] = t1.x; ar[5] = t1.y; ar[6] = t1.z; ar[7] = t1.w;
            float4 u0 = *reinterpret_cast<const float4*>(&Bs[k * SSTRIDE + tx * 8]);
            float4 u1 = *reinterpret_cast<const float4*>(&Bs[k * SSTRIDE + tx * 8 + 4]);
            br[0] = u0.x; br[1] = u0.y; br[2] = u0.z; br[3] = u0.w;
            br[4] = u1.x; br[5] = u1.y; br[6] = u1.z; br[7] = u1.w;
            #pragma unroll
            for (int a = 0; a < 8; ++a)
                #pragma unroll
                for (int b = 0; b < 8; ++b)
                    acc[a][b] = fmaf(ar[a], br[b], acc[a][b]);
        }
    }

    // ---- epilogue: exp, masked neg accumulation (symmetric), pair capture ----
    float negR[8], negC[8];
    #pragma unroll
    for (int a = 0; a < 8; ++a) { negR[a] = 0.0f; negC[a] = 0.0f; }

    #pragma unroll
    for (int a = 0; a < 8; ++a) {
        const int li = labI[ty * 8 + a];
        const int i = i0 + ty * 8 + a;
        #pragma unroll
        for (int b = 0; b < 8; ++b) {
            const int j = j0 + tx * 8 + b;
            if (diag && j <= i) continue;   // strictly upper triangle on diagonal tiles
            const float s = acc[a][b];
            const int lj = labJ[tx * 8 + b];
            if (li != lj) {
                float z = __expf(2.0f * s);
                negR[a] += z;
                negC[b] += z;
            } else {
                int idx = atomicAdd(&g_paircnt, 2);
                if (idx + 1 < PAIR_CAP) {
                    g_pair_i[idx]     = i;  g_pair_s[idx]     = s;
                    g_pair_i[idx + 1] = j;  g_pair_s[idx + 1] = s;
                }
            }
        }
    }

    #pragma unroll
    for (int a = 0; a < 8; ++a) {
        if (negR[a] != 0.0f) atomicAdd(&sNegR[ty * 8 + a], negR[a]);
        if (negC[a] != 0.0f) atomicAdd(&sNegC[tx * 8 + a], negC[a]);
    }
    __syncthreads();
    if (tid < 128) {
        float v = sNegR[tid];
        if (v != 0.0f) atomicAdd(&g_negsum[i0 + tid], v);
        float w = sNegC[tid];
        if (w != 0.0f) atomicAdd(&g_negsum[j0 + tid], w);
    }
}

// ---------------------------------------------------------------
// K3: per-pair loss terms + reduction (sum in double, nnz count).
// ---------------------------------------------------------------
__global__ void __launch_bounds__(256) pair_kernel() {
    const int cnt = min(g_paircnt, PAIR_CAP);
    double local = 0.0;
    int lc = 0;
    for (int p = blockIdx.x * blockDim.x + threadIdx.x; p < cnt;
         p += gridDim.x * blockDim.x) {
        int i = g_pair_i[p];
        float s = g_pair_s[p];
        float z = __expf(2.0f * s);
        float ratio = z / (z + g_negsum[i]);
        float t = -__logf(ratio);
        if (t != 0.0f) { local += (double)t; lc++; }
    }
    #pragma unroll
    for (int off = 16; off > 0; off >>= 1) {
        local += __shfl_xor_sync(0xFFFFFFFFu, local, off);
        lc    += __shfl_xor_sync(0xFFFFFFFFu, lc, off);
    }
    __shared__ double swl[8];
    __shared__ int    swc[8];
    int lane = threadIdx.x & 31, warp = threadIdx.x >> 5;
    if (lane == 0) { swl[warp] = local; swc[warp] = lc; }
    __syncthreads();
    if (threadIdx.x == 0) {
        double bl = 0.0; int bc = 0;
        for (int w = 0; w < 8; ++w) { bl += swl[w]; bc += swc[w]; }
        if (bc > 0) {
            atomicAdd(&g_loss, bl);
            atomicAdd(&g_cnt, bc);
        }
    }
}

// ---------------------------------------------------------------
// K4: finalize scalar
// ---------------------------------------------------------------
__global__ void finalize_kernel(float* __restrict__ out) {
    int c = g_cnt;
    out[0] = (c > 0) ? (float)(g_loss / (double)c) : 0.0f;
}

extern "C" void kernel_launch(void* const* d_in, const int* in_sizes, int n_in,
                              void* d_out, int out_size) {
    const float* X = (const float*)d_in[0];
    const unsigned* labw = (const unsigned*)d_in[1];
    float* out = (float*)d_out;

    int n = in_sizes[1];
    int d = in_sizes[0] / n;

    labels_kernel<<<1, 256>>>(labw, n);
    normalize_kernel<<<n, 64>>>(X, n, d);

    dim3 grid(n / 128, n / 128);
    dim3 block(16, 16);
    gemm_kernel<<<grid, block>>>(n, d);

    pair_kernel<<<256, 256>>>();
    finalize_kernel<<<1, 1>>>(out);
}

// round 12
// speedup vs baseline: 1.0002x; 1.0002x over previous
#include <cuda_runtime.h>
#include <cstdint>

#define MAXN 4096
#define MAXD 256
#define PAIR_CAP 262144
#define SSTRIDE 132   // shared tile row stride (floats), 16B-aligned, conflict-reduced

// -------- scratch (device globals; no allocation allowed) --------
__device__ float  g_norm[MAXN * MAXD];
__device__ float  g_negsum[MAXN];
__device__ int    g_lab[MAXN];
__device__ int    g_paircnt;
__device__ int    g_pair_i[PAIR_CAP];
__device__ float  g_pair_s[PAIR_CAP];
__device__ double g_loss;
__device__ int    g_cnt;

// ---------------------------------------------------------------
// K0: detect label width (int64 vs int32) and convert to g_lab[int].
// Labels are in [0, 512). If stored as int64 (little-endian), every odd
// 32-bit word is zero. If int32, odd words are real labels; the chance
// the first 128 odd words are ALL zero is (1/512)^128 ~ 0.
// Deterministic for fixed input. One block.
// ---------------------------------------------------------------
__global__ void __launch_bounds__(256) labels_kernel(const unsigned* __restrict__ w, int n) {
    __shared__ int s_nonzero;
    if (threadIdx.x == 0) s_nonzero = 0;
    __syncthreads();
    // check odd words among the first 256 words
    int idx = 2 * threadIdx.x + 1;           // 1,3,...,511 for 256 threads
    if (threadIdx.x < 128 && idx < 2 * n) {
        if (w[idx] != 0u) atomicOr(&s_nonzero, 1);
    }
    __syncthreads();
    const bool is64 = (s_nonzero == 0);
    for (int i = threadIdx.x; i < n; i += 256) {
        g_lab[i] = is64 ? (int)w[2 * i] : (int)w[i];
    }
}

// ---------------------------------------------------------------
// K1: row-normalize X -> g_norm; zero per-row negsum + global counters.
// One block (64 threads) per row.
// ---------------------------------------------------------------
__global__ void __launch_bounds__(64) normalize_kernel(const float* __restrict__ X,
                                                       int n, int d) {
    int row = blockIdx.x;
    if (row >= n) return;
    const float* xr = X + (size_t)row * d;

    float ss = 0.0f;
    int nq = d >> 2;
    for (int c = threadIdx.x; c < nq; c += 64) {
        float4 v = reinterpret_cast<const float4*>(xr)[c];
        ss += v.x * v.x + v.y * v.y + v.z * v.z + v.w * v.w;
    }
    #pragma unroll
    for (int off = 16; off > 0; off >>= 1)
        ss += __shfl_xor_sync(0xFFFFFFFFu, ss, off);
    __shared__ float sws[2];
    int lane = threadIdx.x & 31, warp = threadIdx.x >> 5;
    if (lane == 0) sws[warp] = ss;
    __syncthreads();
    float tot = sws[0] + sws[1];
    float inv = 1.0f / fmaxf(sqrtf(tot), 1e-12f);

    float* nr = g_norm + (size_t)row * d;
    for (int c = threadIdx.x; c < nq; c += 64) {
        float4 v = reinterpret_cast<const float4*>(xr)[c];
        float4 o;
        o.x = v.x * inv; o.y = v.y * inv; o.z = v.z * inv; o.w = v.w * inv;
        reinterpret_cast<float4*>(nr)[c] = o;
    }

    if (threadIdx.x == 0) {
        g_negsum[row] = 0.0f;
        if (row == 0) { g_paircnt = 0; g_loss = 0.0; g_cnt = 0; }
    }
}

// ---------------------------------------------------------------
// K2: symmetric sim GEMM (upper-triangular tiles only), fused exp,
// masked negative-sum accumulation (both directions via symmetry),
// same-label pair capture. 128x128 tiles, BK=16, 8x8 microtiles.
// ---------------------------------------------------------------
__global__ void __launch_bounds__(256) gemm_kernel(int n, int d) {
    const int ib = blockIdx.y;
    const int jb = blockIdx.x;
    if (jb < ib) return;
    const bool diag = (ib == jb);

    const int i0 = ib * 128;
    const int j0 = jb * 128;

    __shared__ float As[16 * SSTRIDE];
    __shared__ float Bs[16 * SSTRIDE];
    __shared__ int   labI[128], labJ[128];
    __shared__ float sNegR[128], sNegC[128];

    const int tx = threadIdx.x;  // 0..15
    const int ty = threadIdx.y;  // 0..15
    const int tid = ty * 16 + tx;

    if (tid < 128) {
        sNegR[tid] = 0.0f;
        sNegC[tid] = 0.0f;
        labI[tid] = g_lab[i0 + tid];
        labJ[tid] = g_lab[j0 + tid];
    }

    float acc[8][8];
    #pragma unroll
    for (int a = 0; a < 8; ++a)
        #pragma unroll
        for (int b = 0; b < 8; ++b) acc[a][b] = 0.0f;

    const int nk = d / 16;
    for (int kt = 0; kt < nk; ++kt) {
        __syncthreads();
        #pragma unroll
        for (int l = 0; l < 2; ++l) {
            int idx = tid + l * 256;
            int row = idx >> 2;
            int q = idx & 3;
            int kc = kt * 16 + q * 4;
            float4 a4 = *reinterpret_cast<const float4*>(&g_norm[(size_t)(i0 + row) * d + kc]);
            As[(q * 4 + 0) * SSTRIDE + row] = a4.x;
            As[(q * 4 + 1) * SSTRIDE + row] = a4.y;
            As[(q * 4 + 2) * SSTRIDE + row] = a4.z;
            As[(q * 4 + 3) * SSTRIDE + row] = a4.w;
            float4 b4 = *reinterpret_cast<const float4*>(&g_norm[(size_t)(j0 + row) * d + kc]);
            Bs[(q * 4 + 0) * SSTRIDE + row] = b4.x;
            Bs[(q * 4 + 1) * SSTRIDE + row] = b4.y;
            Bs[(q * 4 + 2) * SSTRIDE + row] = b4.z;
            Bs[(q * 4 + 3) * SSTRIDE + row] = b4.w;
        }
        __syncthreads();

        #pragma unroll
        for (int k = 0; k < 16; ++k) {
            float ar[8], br[8];
            float4 t0 = *reinterpret_cast<const float4*>(&As[k * SSTRIDE + ty * 8]);
            float4 t1 = *reinterpret_cast<const float4*>(&As[k * SSTRIDE + ty * 8 + 4]);
            ar[0] = t0.x; ar[1] = t0.y; ar[2] = t0.z; ar[3] = t0.w;
            ar[4] = t1.x; ar[5] = t1.y; ar[6] = t1.z; ar[7] = t1.w;
            float4 u0 = *reinterpret_cast<const float4*>(&Bs[k * SSTRIDE + tx * 8]);
            float4 u1 = *reinterpret_cast<const float4*>(&Bs[k * SSTRIDE + tx * 8 + 4]);
            br[0] = u0.x; br[1] = u0.y; br[2] = u0.z; br[3] = u0.w;
            br[4] = u1.x; br[5] = u1.y; br[6] = u1.z; br[7] = u1.w;
            #pragma unroll
            for (int a = 0; a < 8; ++a)
                #pragma unroll
                for (int b = 0; b < 8; ++b)
                    acc[a][b] = fmaf(ar[a], br[b], acc[a][b]);
        }
    }

    // ---- epilogue: exp, masked neg accumulation (symmetric), pair capture ----
    float negR[8], negC[8];
    #pragma unroll
    for (int a = 0; a < 8; ++a) { negR[a] = 0.0f; negC[a] = 0.0f; }

    #pragma unroll
    for (int a = 0; a < 8; ++a) {
        const int li = labI[ty * 8 + a];
        const int i = i0 + ty * 8 + a;
        #pragma unroll
        for (int b = 0; b < 8; ++b) {
            const int j = j0 + tx * 8 + b;
            if (diag && j <= i) continue;   // strictly upper triangle on diagonal tiles
            const float s = acc[a][b];
            const int lj = labJ[tx * 8 + b];
            if (li != lj) {
                float z = __expf(2.0f * s);
                negR[a] += z;
                negC[b] += z;
            } else {
                int idx = atomicAdd(&g_paircnt, 2);
                if (idx + 1 < PAIR_CAP) {
                    g_pair_i[idx]     = i;  g_pair_s[idx]     = s;
                    g_pair_i[idx + 1] = j;  g_pair_s[idx + 1] = s;
                }
            }
        }
    }

    #pragma unroll
    for (int a = 0; a < 8; ++a) {
        if (negR[a] != 0.0f) atomicAdd(&sNegR[ty * 8 + a], negR[a]);
        if (negC[a] != 0.0f) atomicAdd(&sNegC[tx * 8 + a], negC[a]);
    }
    __syncthreads();
    if (tid < 128) {
        float v = sNegR[tid];
        if (v != 0.0f) atomicAdd(&g_negsum[i0 + tid], v);
        float w = sNegC[tid];
        if (w != 0.0f) atomicAdd(&g_negsum[j0 + tid], w);
    }
}

// ---------------------------------------------------------------
// K3: per-pair loss terms + reduction (sum in double, nnz count).
// ---------------------------------------------------------------
__global__ void __launch_bounds__(256) pair_kernel() {
    const int cnt = min(g_paircnt, PAIR_CAP);
    double local = 0.0;
    int lc = 0;
    for (int p = blockIdx.x * blockDim.x + threadIdx.x; p < cnt;
         p += gridDim.x * blockDim.x) {
        int i = g_pair_i[p];
        float s = g_pair_s[p];
        float z = __expf(2.0f * s);
        float ratio = z / (z + g_negsum[i]);
        float t = -__logf(ratio);
        if (t != 0.0f) { local += (double)t; lc++; }
    }
    #pragma unroll
    for (int off = 16; off > 0; off >>= 1) {
        local += __shfl_xor_sync(0xFFFFFFFFu, local, off);
        lc    += __shfl_xor_sync(0xFFFFFFFFu, lc, off);
    }
    __shared__ double swl[8];
    __shared__ int    swc[8];
    int lane = threadIdx.x & 31, warp = threadIdx.x >> 5;
    if (lane == 0) { swl[warp] = local; swc[warp] = lc; }
    __syncthreads();
    if (threadIdx.x == 0) {
        double bl = 0.0; int bc = 0;
        for (int w = 0; w < 8; ++w) { bl += swl[w]; bc += swc[w]; }
        if (bc > 0) {
            atomicAdd(&g_loss, bl);
            atomicAdd(&g_cnt, bc);
        }
    }
}

// ---------------------------------------------------------------
// K4: finalize scalar
// ---------------------------------------------------------------
__global__ void finalize_kernel(float* __restrict__ out) {
    int c = g_cnt;
    out[0] = (c > 0) ? (float)(g_loss / (double)c) : 0.0f;
}

extern "C" void kernel_launch(void* const* d_in, const int* in_sizes, int n_in,
                              void* d_out, int out_size) {
    const float* X = (const float*)d_in[0];
    const unsigned* labw = (const unsigned*)d_in[1];
    float* out = (float*)d_out;

    int n = in_sizes[1];
    int d = in_sizes[0] / n;

    labels_kernel<<<1, 256>>>(labw, n);
    normalize_kernel<<<n, 64>>>(X, n, d);

    dim3 grid(n / 128, n / 128);
    dim3 block(16, 16);
    gemm_kernel<<<grid, block>>>(n, d);

    pair_kernel<<<256, 256>>>();
    finalize_kernel<<<1, 1>>>(out);
}

// round 13
// speedup vs baseline: 1.0086x; 1.0084x over previous
#include <cuda_runtime.h>
#include <cstdint>

#define MAXN 4096
#define MAXD 256
#define PAIR_CAP 262144
#define SSTRIDE 132   // shared tile row stride (floats), 16B-aligned, conflict-reduced

// -------- scratch (device globals; no allocation allowed) --------
__device__ float  g_norm[MAXN * MAXD];
__device__ float  g_negsum[MAXN];
__device__ int    g_lab[MAXN];
__device__ int    g_paircnt;
__device__ int    g_pair_i[PAIR_CAP];
__device__ float  g_pair_s[PAIR_CAP];
__device__ double g_loss;
__device__ int    g_cnt;

// packed f32x2 helpers (sm_103a FFMA2 — PTX-only, not emitted by ptxas from C++)
__device__ __forceinline__ unsigned long long dup_f32x2(float a) {
    unsigned long long r;
    asm("mov.b64 %0, {%1, %1};" : "=l"(r) : "f"(a));
    return r;
}
__device__ __forceinline__ void fma_f32x2(unsigned long long& acc,
                                          unsigned long long a,
                                          unsigned long long b) {
    asm("fma.rn.f32x2 %0, %1, %2, %0;" : "+l"(acc) : "l"(a), "l"(b));
}
__device__ __forceinline__ void unpack_f32x2(unsigned long long v, float& lo, float& hi) {
    asm("mov.b64 {%0, %1}, %2;" : "=f"(lo), "=f"(hi) : "l"(v));
}

// ---------------------------------------------------------------
// K0: detect label width (int64 vs int32) and convert to g_lab[int].
// ---------------------------------------------------------------
__global__ void __launch_bounds__(256) labels_kernel(const unsigned* __restrict__ w, int n) {
    __shared__ int s_nonzero;
    if (threadIdx.x == 0) s_nonzero = 0;
    __syncthreads();
    int idx = 2 * threadIdx.x + 1;
    if (threadIdx.x < 128 && idx < 2 * n) {
        if (w[idx] != 0u) atomicOr(&s_nonzero, 1);
    }
    __syncthreads();
    const bool is64 = (s_nonzero == 0);
    for (int i = threadIdx.x; i < n; i += 256) {
        g_lab[i] = is64 ? (int)w[2 * i] : (int)w[i];
    }
}

// ---------------------------------------------------------------
// K1: row-normalize X -> g_norm; zero per-row negsum + global counters.
// ---------------------------------------------------------------
__global__ void __launch_bounds__(64) normalize_kernel(const float* __restrict__ X,
                                                       int n, int d) {
    int row = blockIdx.x;
    if (row >= n) return;
    const float* xr = X + (size_t)row * d;

    float ss = 0.0f;
    int nq = d >> 2;
    for (int c = threadIdx.x; c < nq; c += 64) {
        float4 v = reinterpret_cast<const float4*>(xr)[c];
        ss += v.x * v.x + v.y * v.y + v.z * v.z + v.w * v.w;
    }
    #pragma unroll
    for (int off = 16; off > 0; off >>= 1)
        ss += __shfl_xor_sync(0xFFFFFFFFu, ss, off);
    __shared__ float sws[2];
    int lane = threadIdx.x & 31, warp = threadIdx.x >> 5;
    if (lane == 0) sws[warp] = ss;
    __syncthreads();
    float tot = sws[0] + sws[1];
    float inv = 1.0f / fmaxf(sqrtf(tot), 1e-12f);

    float* nr = g_norm + (size_t)row * d;
    for (int c = threadIdx.x; c < nq; c += 64) {
        float4 v = reinterpret_cast<const float4*>(xr)[c];
        float4 o;
        o.x = v.x * inv; o.y = v.y * inv; o.z = v.z * inv; o.w = v.w * inv;
        reinterpret_cast<float4*>(nr)[c] = o;
    }

    if (threadIdx.x == 0) {
        g_negsum[row] = 0.0f;
        if (row == 0) { g_paircnt = 0; g_loss = 0.0; g_cnt = 0; }
    }
}

// ---------------------------------------------------------------
// K2: symmetric sim GEMM (upper-triangular tiles only), FFMA2 inner loop,
// fused exp, masked negative-sum accumulation, same-label pair capture.
// 128x128 tiles, BK=16, 8x8 microtiles (stored as 8x4 f32x2 packs).
// ---------------------------------------------------------------
__global__ void __launch_bounds__(256, 2) gemm_kernel(int n, int d) {
    const int ib = blockIdx.y;
    const int jb = blockIdx.x;
    if (jb < ib) return;
    const bool diag = (ib == jb);

    const int i0 = ib * 128;
    const int j0 = jb * 128;

    __shared__ float As[16 * SSTRIDE];
    __shared__ float Bs[16 * SSTRIDE];
    __shared__ int   labI[128], labJ[128];
    __shared__ float sNegR[128], sNegC[128];

    const int tx = threadIdx.x;  // 0..15
    const int ty = threadIdx.y;  // 0..15
    const int tid = ty * 16 + tx;

    if (tid < 128) {
        sNegR[tid] = 0.0f;
        sNegC[tid] = 0.0f;
        labI[tid] = g_lab[i0 + tid];
        labJ[tid] = g_lab[j0 + tid];
    }

    // acc[a][bp] holds columns {2bp, 2bp+1} packed as f32x2
    unsigned long long acc[8][4];
    #pragma unroll
    for (int a = 0; a < 8; ++a)
        #pragma unroll
        for (int b = 0; b < 4; ++b) acc[a][b] = 0ULL;

    const int nk = d / 16;
    for (int kt = 0; kt < nk; ++kt) {
        __syncthreads();
        #pragma unroll
        for (int l = 0; l < 2; ++l) {
            int idx = tid + l * 256;
            int row = idx >> 2;
            int q = idx & 3;
            int kc = kt * 16 + q * 4;
            float4 a4 = *reinterpret_cast<const float4*>(&g_norm[(size_t)(i0 + row) * d + kc]);
            As[(q * 4 + 0) * SSTRIDE + row] = a4.x;
            As[(q * 4 + 1) * SSTRIDE + row] = a4.y;
            As[(q * 4 + 2) * SSTRIDE + row] = a4.z;
            As[(q * 4 + 3) * SSTRIDE + row] = a4.w;
            float4 b4 = *reinterpret_cast<const float4*>(&g_norm[(size_t)(j0 + row) * d + kc]);
            Bs[(q * 4 + 0) * SSTRIDE + row] = b4.x;
            Bs[(q * 4 + 1) * SSTRIDE + row] = b4.y;
            Bs[(q * 4 + 2) * SSTRIDE + row] = b4.z;
            Bs[(q * 4 + 3) * SSTRIDE + row] = b4.w;
        }
        __syncthreads();

        #pragma unroll
        for (int k = 0; k < 16; ++k) {
            // a values (broadcast operand): duplicate each into both f32x2 lanes
            float4 t0 = *reinterpret_cast<const float4*>(&As[k * SSTRIDE + ty * 8]);
            float4 t1 = *reinterpret_cast<const float4*>(&As[k * SSTRIDE + ty * 8 + 4]);
            unsigned long long ad[8];
            ad[0] = dup_f32x2(t0.x); ad[1] = dup_f32x2(t0.y);
            ad[2] = dup_f32x2(t0.z); ad[3] = dup_f32x2(t0.w);
            ad[4] = dup_f32x2(t1.x); ad[5] = dup_f32x2(t1.y);
            ad[6] = dup_f32x2(t1.z); ad[7] = dup_f32x2(t1.w);
            // b values: adjacent column pairs are natively packed in shared
            ulonglong2 w0 = *reinterpret_cast<const ulonglong2*>(&Bs[k * SSTRIDE + tx * 8]);
            ulonglong2 w1 = *reinterpret_cast<const ulonglong2*>(&Bs[k * SSTRIDE + tx * 8 + 4]);
            unsigned long long bp[4] = {w0.x, w0.y, w1.x, w1.y};
            #pragma unroll
            for (int a = 0; a < 8; ++a)
                #pragma unroll
                for (int b = 0; b < 4; ++b)
                    fma_f32x2(acc[a][b], ad[a], bp[b]);
        }
    }

    // ---- epilogue: exp, masked neg accumulation (symmetric), pair capture ----
    float negR[8], negC[8];
    #pragma unroll
    for (int a = 0; a < 8; ++a) { negR[a] = 0.0f; negC[a] = 0.0f; }

    #pragma unroll
    for (int a = 0; a < 8; ++a) {
        const int li = labI[ty * 8 + a];
        const int i = i0 + ty * 8 + a;
        #pragma unroll
        for (int bpk = 0; bpk < 4; ++bpk) {
            float sv[2];
            unpack_f32x2(acc[a][bpk], sv[0], sv[1]);
            #pragma unroll
            for (int h = 0; h < 2; ++h) {
                const int b = bpk * 2 + h;
                const int j = j0 + tx * 8 + b;
                if (diag && j <= i) continue;   // strictly upper triangle on diagonal tiles
                const float s = sv[h];
                const int lj = labJ[tx * 8 + b];
                if (li != lj) {
                    float z = __expf(2.0f * s);
                    negR[a] += z;
                    negC[b] += z;
                } else {
                    int idx = atomicAdd(&g_paircnt, 2);
                    if (idx + 1 < PAIR_CAP) {
                        g_pair_i[idx]     = i;  g_pair_s[idx]     = s;
                        g_pair_i[idx + 1] = j;  g_pair_s[idx + 1] = s;
                    }
                }
            }
        }
    }

    #pragma unroll
    for (int a = 0; a < 8; ++a) {
        if (negR[a] != 0.0f) atomicAdd(&sNegR[ty * 8 + a], negR[a]);
        if (negC[a] != 0.0f) atomicAdd(&sNegC[tx * 8 + a], negC[a]);
    }
    __syncthreads();
    if (tid < 128) {
        float v = sNegR[tid];
        if (v != 0.0f) atomicAdd(&g_negsum[i0 + tid], v);
        float w = sNegC[tid];
        if (w != 0.0f) atomicAdd(&g_negsum[j0 + tid], w);
    }
}

// ---------------------------------------------------------------
// K3: per-pair loss terms + reduction (sum in double, nnz count).
// ---------------------------------------------------------------
__global__ void __launch_bounds__(256) pair_kernel() {
    const int cnt = min(g_paircnt, PAIR_CAP);
    double local = 0.0;
    int lc = 0;
    for (int p = blockIdx.x * blockDim.x + threadIdx.x; p < cnt;
         p += gridDim.x * blockDim.x) {
        int i = g_pair_i[p];
        float s = g_pair_s[p];
        float z = __expf(2.0f * s);
        float ratio = z / (z + g_negsum[i]);
        float t = -__logf(ratio);
        if (t != 0.0f) { local += (double)t; lc++; }
    }
    #pragma unroll
    for (int off = 16; off > 0; off >>= 1) {
        local += __shfl_xor_sync(0xFFFFFFFFu, local, off);
        lc    += __shfl_xor_sync(0xFFFFFFFFu, lc, off);
    }
    __shared__ double swl[8];
    __shared__ int    swc[8];
    int lane = threadIdx.x & 31, warp = threadIdx.x >> 5;
    if (lane == 0) { swl[warp] = local; swc[warp] = lc; }
    __syncthreads();
    if (threadIdx.x == 0) {
        double bl = 0.0; int bc = 0;
        for (int w = 0; w < 8; ++w) { bl += swl[w]; bc += swc[w]; }
        if (bc > 0) {
            atomicAdd(&g_loss, bl);
            atomicAdd(&g_cnt, bc);
        }
    }
}

// ---------------------------------------------------------------
// K4: finalize scalar
// ---------------------------------------------------------------
__global__ void finalize_kernel(float* __restrict__ out) {
    int c = g_cnt;
    out[0] = (c > 0) ? (float)(g_loss / (double)c) : 0.0f;
}

extern "C" void kernel_launch(void* const* d_in, const int* in_sizes, int n_in,
                              void* d_out, int out_size) {
    const float* X = (const float*)d_in[0];
    const unsigned* labw = (const unsigned*)d_in[1];
    float* out = (float*)d_out;

    int n = in_sizes[1];
    int d = in_sizes[0] / n;

    labels_kernel<<<1, 256>>>(labw, n);
    normalize_kernel<<<n, 64>>>(X, n, d);

    dim3 grid(n / 128, n / 128);
    dim3 block(16, 16);
    gemm_kernel<<<grid, block>>>(n, d);

    pair_kernel<<<256, 256>>>();
    finalize_kernel<<<1, 1>>>(out);
}